// round 2
// baseline (speedup 1.0000x reference)
#include <cuda_runtime.h>
#include <cuda_bf16.h>
#include <cstdint>

// Problem constants (fixed shapes)
#define B_SZ   256
#define T_SZ   512
#define EMB    128
#define HID    256
#define NCLS   32000

// Scratch: h0 at last timestep, stored bf16 for tensor-core GEMM
__device__ __nv_bfloat16 g_h0[B_SZ * HID];

// ---------------------------------------------------------------------------
// Kernel 1: h0_last[b, h] for the 256 last-timestep tokens. (unchanged R1)
// ---------------------------------------------------------------------------
__global__ void __launch_bounds__(256) lstm_h0_kernel(
    const int* __restrict__ X, const float* __restrict__ C_table,
    const float* __restrict__ U_i, const float* __restrict__ b_i,
    const float* __restrict__ U_c, const float* __restrict__ b_c,
    const float* __restrict__ U_o, const float* __restrict__ b_o)
{
    __shared__ float E_s[4][EMB];
    const int b0 = blockIdx.x * 4;
    const int tid = threadIdx.x;

    for (int i = tid; i < 4 * EMB; i += 256) {
        int b = i >> 7;
        int e = i & (EMB - 1);
        int tok = X[(b0 + b) * T_SZ + (T_SZ - 1)];
        E_s[b][e] = C_table[tok * EMB + e];
    }
    __syncthreads();

    const int h = tid;
    float ai[4], ag[4], ao[4];
    const float bi = b_i[h], bc = b_c[h], bo = b_o[h];
#pragma unroll
    for (int b = 0; b < 4; b++) { ai[b] = bi; ag[b] = bc; ao[b] = bo; }

#pragma unroll 4
    for (int e = 0; e < EMB; e++) {
        float ui = U_i[e * HID + h];
        float uc = U_c[e * HID + h];
        float uo = U_o[e * HID + h];
#pragma unroll
        for (int b = 0; b < 4; b++) {
            float ev = E_s[b][e];
            ai[b] = fmaf(ev, ui, ai[b]);
            ag[b] = fmaf(ev, uc, ag[b]);
            ao[b] = fmaf(ev, uo, ao[b]);
        }
    }

#pragma unroll
    for (int b = 0; b < 4; b++) {
        float i0 = 1.0f / (1.0f + __expf(-ai[b]));
        float g0 = tanhf(ag[b]);
        float o0 = 1.0f / (1.0f + __expf(-ao[b]));
        float c0 = i0 * g0;
        float h0 = o0 * tanhf(c0);
        g_h0[(b0 + b) * HID + h] = __float2bfloat16(h0);
    }
}

// ---------------------------------------------------------------------------
// Kernel 2: logits[256, 32000] = h0[256,256] @ W_w[32000,256]^T + b_out
// Persistent pipelined bf16 mma.sync GEMM.
//   - grid = 148 persistent blocks, each loops over N-tiles of 128 (250 tiles)
//   - A (h0, bf16) resident in smem for block lifetime, loaded via cp.async
//   - B (W slice) streamed fp32 via cp.async in 4 K-chunks of 64, double-
//     buffered; fp32->bf16 conversion at fragment-load time
// ---------------------------------------------------------------------------
#define BN      128
#define NTILES  (NCLS / BN)      // 250
#define GRID2   148
#define ASTR    264              // A_s row stride in bf16 (528B, 16B aligned)
#define CHUNK_K 64
#define NCHUNK  (HID / CHUNK_K)  // 4
#define BSTR    72               // B_s row stride in fp32 (288B, 16B aligned)
#define BBUF    (BN * BSTR)      // one B buffer, in floats

__device__ __forceinline__ void cp16(void* dst_smem, const void* src) {
    uint32_t d = (uint32_t)__cvta_generic_to_shared(dst_smem);
    asm volatile("cp.async.cg.shared.global [%0], [%1], 16;" :: "r"(d), "l"(src));
}
__device__ __forceinline__ void cp_commit() {
    asm volatile("cp.async.commit_group;" ::: "memory");
}
__device__ __forceinline__ void cp_wait1() {
    asm volatile("cp.async.wait_group 1;" ::: "memory");
}

__global__ void __launch_bounds__(512, 1) logits_kernel(
    const float* __restrict__ W_w, const float* __restrict__ b_out,
    float* __restrict__ out)
{
    extern __shared__ char smem_raw[];
    __nv_bfloat16* A_s = (__nv_bfloat16*)smem_raw;                 // [256][ASTR]
    float*         B_s = (float*)(smem_raw + B_SZ * ASTR * 2);     // 2*[128][BSTR]

    const int tid = threadIdx.x;

    // --- issue A load: g_h0 (256x256 bf16 = 128KB) in 16B segments ---
    {
        const char* src = (const char*)g_h0;
#pragma unroll
        for (int k = 0; k < 16; k++) {
            int idx = tid + k * 512;       // 8192 segs total
            int row = idx >> 5;            // 32 segs per row (512B)
            int seg = idx & 31;
            cp16((char*)A_s + row * (ASTR * 2) + seg * 16,
                 src + row * (HID * 2) + seg * 16);
        }
    }
    // --- issue first B chunk (tile = blockIdx.x, chunk 0) into buf 0 ---
    {
        int t0 = blockIdx.x;               // always < NTILES (148 <= 250)
#pragma unroll
        for (int k = 0; k < 4; k++) {
            int idx = tid + k * 512;       // 2048 segs (128 rows x 16 segs)
            int row = idx >> 4;
            int seg = idx & 15;
            cp16(B_s + row * BSTR + seg * 4,
                 W_w + (size_t)(t0 * BN + row) * HID + seg * 4);
        }
    }
    cp_commit();   // group g0 = A + chunk0

    const int wid  = tid >> 5;
    const int lane = tid & 31;
    const int wm   = wid >> 2;      // 0..3 -> M offset wm*64
    const int wn   = wid & 3;       // 0..3 -> N offset wn*32
    const int gr   = lane >> 2;
    const int tig  = lane & 3;

    float acc[4][4][4];
#pragma unroll
    for (int mi = 0; mi < 4; mi++)
#pragma unroll
        for (int ni = 0; ni < 4; ni++)
#pragma unroll
            for (int r = 0; r < 4; r++) acc[mi][ni][r] = 0.0f;

    int buf = 0;
    for (int tile = blockIdx.x; tile < NTILES; tile += GRID2) {
        const int n0 = tile * BN;
#pragma unroll
        for (int c = 0; c < NCHUNK; c++) {
            // ---- issue next chunk (possibly next tile's chunk 0) ----
            int ntile = (c == NCHUNK - 1) ? (tile + GRID2) : tile;
            int nc    = (c + 1) & (NCHUNK - 1);
            if (ntile < NTILES) {
                float* dst = B_s + (buf ^ 1) * BBUF;
                const float* src =
                    W_w + (size_t)(ntile * BN) * HID + nc * CHUNK_K;
#pragma unroll
                for (int k = 0; k < 4; k++) {
                    int idx = tid + k * 512;
                    int row = idx >> 4;
                    int seg = idx & 15;
                    cp16(dst + row * BSTR + seg * 4,
                         src + (size_t)row * HID + seg * 4);
                }
            }
            cp_commit();
            cp_wait1();        // chunk c (and A on first iter) complete
            __syncthreads();

            // ---- compute 4 kk steps of chunk c ----
            const float* Bb = B_s + buf * BBUF;
#pragma unroll
            for (int kkl = 0; kkl < CHUNK_K / 16; kkl++) {
                const int kbg = c * CHUNK_K + kkl * 16;   // global K offset (A)
                const int kbl = kkl * 16;                 // local K offset (B)
                uint32_t a[4][4];
#pragma unroll
                for (int mi = 0; mi < 4; mi++) {
                    const __nv_bfloat16* p =
                        &A_s[(wm * 64 + mi * 16 + gr) * ASTR + kbg + tig * 2];
                    a[mi][0] = *(const uint32_t*)(p);
                    a[mi][1] = *(const uint32_t*)(p + 8 * ASTR);
                    a[mi][2] = *(const uint32_t*)(p + 8);
                    a[mi][3] = *(const uint32_t*)(p + 8 * ASTR + 8);
                }
                uint32_t bf[4][2];
#pragma unroll
                for (int ni = 0; ni < 4; ni++) {
                    const float* p =
                        Bb + (wn * 32 + ni * 8 + gr) * BSTR + kbl + tig * 2;
                    float2 f0 = *(const float2*)(p);
                    float2 f1 = *(const float2*)(p + 8);
                    __nv_bfloat162 p0 = __floats2bfloat162_rn(f0.x, f0.y);
                    __nv_bfloat162 p1 = __floats2bfloat162_rn(f1.x, f1.y);
                    bf[ni][0] = *(const uint32_t*)&p0;
                    bf[ni][1] = *(const uint32_t*)&p1;
                }
#pragma unroll
                for (int mi = 0; mi < 4; mi++) {
#pragma unroll
                    for (int ni = 0; ni < 4; ni++) {
                        asm volatile(
                            "mma.sync.aligned.m16n8k16.row.col.f32.bf16.bf16.f32 "
                            "{%0,%1,%2,%3}, {%4,%5,%6,%7}, {%8,%9}, {%0,%1,%2,%3};"
                            : "+f"(acc[mi][ni][0]), "+f"(acc[mi][ni][1]),
                              "+f"(acc[mi][ni][2]), "+f"(acc[mi][ni][3])
                            : "r"(a[mi][0]), "r"(a[mi][1]), "r"(a[mi][2]), "r"(a[mi][3]),
                              "r"(bf[ni][0]), "r"(bf[ni][1]));
                    }
                }
            }

            // ---- epilogue on last chunk of tile ----
            if (c == NCHUNK - 1) {
                float bo0[4], bo1[4];
#pragma unroll
                for (int ni = 0; ni < 4; ni++) {
                    int col = n0 + wn * 32 + ni * 8 + tig * 2;
                    bo0[ni] = b_out[col];
                    bo1[ni] = b_out[col + 1];
                }
#pragma unroll
                for (int mi = 0; mi < 4; mi++) {
                    int row = wm * 64 + mi * 16 + gr;
#pragma unroll
                    for (int ni = 0; ni < 4; ni++) {
                        int col = n0 + wn * 32 + ni * 8 + tig * 2;
                        float2 v0 = make_float2(acc[mi][ni][0] + bo0[ni],
                                                acc[mi][ni][1] + bo1[ni]);
                        float2 v1 = make_float2(acc[mi][ni][2] + bo0[ni],
                                                acc[mi][ni][3] + bo1[ni]);
                        *(float2*)(&out[(size_t)row * NCLS + col])       = v0;
                        *(float2*)(&out[(size_t)(row + 8) * NCLS + col]) = v1;
                    }
                }
#pragma unroll
                for (int mi = 0; mi < 4; mi++)
#pragma unroll
                    for (int ni = 0; ni < 4; ni++)
#pragma unroll
                        for (int r = 0; r < 4; r++) acc[mi][ni][r] = 0.0f;
            }
            __syncthreads();   // all reads of buf done before it is re-filled
            buf ^= 1;
        }
    }
}

// ---------------------------------------------------------------------------
// Launcher
// Input order: 0=X 1=C_table 2=U_i 3=V_i 4=b_i 5=U_f 6=V_f 7=b_f
//  8=U_c 9=V_c 10=b_c 11=U_o 12=V_o 13=b_o 14..25=layer1 (unused) 26=W_w 27=b_out
// ---------------------------------------------------------------------------
extern "C" void kernel_launch(void* const* d_in, const int* in_sizes, int n_in,
                              void* d_out, int out_size)
{
    const int*   X       = (const int*)d_in[0];
    const float* C_table = (const float*)d_in[1];
    const float* U_i     = (const float*)d_in[2];
    const float* b_i     = (const float*)d_in[4];
    const float* U_c     = (const float*)d_in[8];
    const float* b_c     = (const float*)d_in[10];
    const float* U_o     = (const float*)d_in[11];
    const float* b_o     = (const float*)d_in[13];
    const float* W_w     = (const float*)d_in[26];
    const float* b_out   = (const float*)d_in[27];
    float* out = (float*)d_out;

    lstm_h0_kernel<<<B_SZ / 4, 256>>>(X, C_table, U_i, b_i, U_c, b_c, U_o, b_o);

    const int smem_bytes = B_SZ * ASTR * 2 + 2 * BBUF * (int)sizeof(float);
    cudaFuncSetAttribute(logits_kernel,
                         cudaFuncAttributeMaxDynamicSharedMemorySize, smem_bytes);
    logits_kernel<<<GRID2, 512, smem_bytes>>>(W_w, b_out, out);
}